// round 6
// baseline (speedup 1.0000x reference)
#include <cuda_runtime.h>
#include <math.h>

#define B_     64
#define H_     256
#define E_     256
#define V_     64
#define TOTAL_ 2046

// ---------------- static device scratch (alloc-free rule) ----------------
__device__ float g_xg[V_ * 4 * H_];        // [v][g][h]  precomputed x@W + bW
__device__ float g_Ucat[512 * 1280];       // [h512][g*256+k]  combined U
__device__ float g_h[2][B_ * 1024 * H_];   // ping-pong hidden
__device__ float g_c[2][B_ * 1024 * H_];   // ping-pong cell

__device__ __forceinline__ float sigmoidf_(float x) {
    return 1.0f / (1.0f + expf(-x));
}

// ---------------- prep: xg_table[v][g][h] = emb[v] @ W[g] + bW[g] --------
__global__ void xg_kernel(const float* __restrict__ emb,
                          const float* __restrict__ W,
                          const float* __restrict__ bW) {
    __shared__ float se[E_];
    int v = blockIdx.x;
    int h = threadIdx.x;                     // 256 threads
    se[h] = emb[v * E_ + h];
    __syncthreads();
    float a0 = bW[0 * H_ + h];
    float a1 = bW[1 * H_ + h];
    float a2 = bW[2 * H_ + h];
    float a3 = bW[3 * H_ + h];
    for (int e = 0; e < E_; e++) {
        float x = se[e];
        a0 += x * W[(0 * E_ + e) * H_ + h];
        a1 += x * W[(1 * E_ + e) * H_ + h];
        a2 += x * W[(2 * E_ + e) * H_ + h];
        a3 += x * W[(3 * E_ + e) * H_ + h];
    }
    g_xg[(v * 4 + 0) * H_ + h] = a0;
    g_xg[(v * 4 + 1) * H_ + h] = a1;
    g_xg[(v * 4 + 2) * H_ + h] = a2;
    g_xg[(v * 4 + 3) * H_ + h] = a3;
}

// ---------------- prep: Ucat[h512][g*256+k] -------------------------------
// h512 < 256 -> U[g][0][h512][k] (left child), else U[g][1][h512-256][k]
__global__ void ucat_kernel(const float* __restrict__ U) {
    int idx = blockIdx.x * blockDim.x + threadIdx.x;
    if (idx < 512 * 1280) {
        int h512 = idx / 1280;
        int c = idx - h512 * 1280;
        int g = c >> 8;
        int k = c & 255;
        int s = h512 >> 8;
        int hh = h512 & 255;
        g_Ucat[idx] = U[(((g * 2 + s) * H_) + hh) * H_ + k];
    }
}

// ---------------- leaf level (lev 10): children are zero ------------------
// c = sig(xg1)*tanh(xg3);  h = sig(xg2)*tanh(c)
__global__ void leaf_kernel(const int* __restrict__ ids) {
    int idx = blockIdx.x * 256 + threadIdx.x;   // 64*1024*256 total
    int r = idx >> 8;            // global node row  (b*1024 + j)
    int k = idx & 255;
    int b = r >> 10;
    int j = r & 1023;
    int id = ids[b * TOTAL_ + 1022 + j];
    const float* xg = &g_xg[id * 4 * H_];
    float ig = sigmoidf_(xg[1 * H_ + k]);
    float og = sigmoidf_(xg[2 * H_ + k]);
    float ug = tanhf(xg[3 * H_ + k]);
    float cv = ig * ug;
    g_c[0][idx] = cv;
    g_h[0][idx] = og * tanhf(cv);
}

// ---------------- inner level: fused [hl|hr]@Ucat GEMM + gates ------------
// tile: 64 nodes x 32 k-cols, all 5 gates; K=512 streamed in 32-chunks.
// accumulators are packed f32x2 (Blackwell fma.rn.f32x2, 2x fp32 rate).
#define BM_ 64
#define TK_ 32
__global__ __launch_bounds__(256) void inner_kernel(
        const int* __restrict__ ids, int off, int log2n,
        int in_buf, int out_buf) {
    __shared__ __align__(16) float As[BM_][TK_];       // [node][kk]
    __shared__ __align__(16) float Bs[TK_][160];       // [kk][g*32+kcol]

    const float* __restrict__ hin  = g_h[in_buf];
    const float* __restrict__ cin  = g_c[in_buf];
    float* __restrict__ hout = g_h[out_buf];
    float* __restrict__ cout = g_c[out_buf];

    int tid = threadIdx.x;
    int tx = tid & 15;           // col-pair: k = k0 + tx*2
    int ty = tid >> 4;           // node group: nodes ty+16*i
    int rowBase = blockIdx.x * BM_;
    int k0 = blockIdx.y * TK_;

    unsigned long long acc[20];  // [node i][gate g] packed f32x2
    #pragma unroll
    for (int i = 0; i < 20; i++) acc[i] = 0ull;

    for (int kc = 0; kc < 512; kc += TK_) {
        // A tile (vectorized): 64 rows x 32 k of child hidden.
        // Within a 32-chunk, (kc+kk)>>8 is constant -> one child row,
        // 32 contiguous floats = 8 float4 loads per row.
        int side = kc >> 8;            // 0: left child, 1: right child
        int colb = (kc & 255) >> 2;    // float4 column base within child row
        #pragma unroll
        for (int t = 0; t < 2; t++) {
            int idx = tid + t * 256;   // 0..511 float4 slots
            int row = idx >> 3;
            int q = idx & 7;
            int child = 2 * (rowBase + row) + side;
            float4 v = *reinterpret_cast<const float4*>(
                &hin[child * H_ + ((colb + q) << 2)]);
            *reinterpret_cast<float4*>(&As[row][q << 2]) = v;
        }
        // B tile (vectorized): 32 k-rows x 5 gates x 32 cols = 1280 float4.
        #pragma unroll
        for (int t = 0; t < 5; t++) {
            int idx = tid + t * 256;   // 0..1279
            int kk = idx / 40;
            int c4 = idx - kk * 40;
            int g = c4 >> 3;
            int q = c4 & 7;
            float4 v = *reinterpret_cast<const float4*>(
                &g_Ucat[(kc + kk) * 1280 + g * 256 + k0 + (q << 2)]);
            *reinterpret_cast<float4*>(&Bs[kk][g * 32 + (q << 2)]) = v;
        }
        __syncthreads();

        #pragma unroll 4
        for (int kk = 0; kk < TK_; kk++) {
            unsigned long long b2[5];
            #pragma unroll
            for (int g = 0; g < 5; g++)
                b2[g] = *reinterpret_cast<const unsigned long long*>(
                            &Bs[kk][g * 32 + tx * 2]);
            #pragma unroll
            for (int i = 0; i < 4; i++) {
                float a = As[ty + 16 * i][kk];
                unsigned long long a2;
                asm("mov.b64 %0, {%1, %1};" : "=l"(a2) : "f"(a));
                #pragma unroll
                for (int g = 0; g < 5; g++)
                    asm("fma.rn.f32x2 %0, %1, %2, %0;"
                        : "+l"(acc[i * 5 + g]) : "l"(a2), "l"(b2[g]));
            }
        }
        __syncthreads();
    }

    // epilogue: add xg gather, gates, c/h update
    int n = 1 << log2n;
    #pragma unroll
    for (int i = 0; i < 4; i++) {
        int r = rowBase + ty + 16 * i;
        int b = r >> log2n;
        int j = r & (n - 1);
        int id = ids[b * TOTAL_ + off + j];
        int k = k0 + tx * 2;
        const float* xg = &g_xg[id * 4 * H_];

        float pre[5][2];
        #pragma unroll
        for (int g = 0; g < 5; g++)
            asm("mov.b64 {%0, %1}, %2;"
                : "=f"(pre[g][0]), "=f"(pre[g][1]) : "l"(acc[i * 5 + g]));
        // gate_map = [0,0,1,2,3]
        #pragma unroll
        for (int cc = 0; cc < 2; cc++) {
            pre[0][cc] += xg[0 * H_ + k + cc];
            pre[1][cc] += xg[0 * H_ + k + cc];
            pre[2][cc] += xg[1 * H_ + k + cc];
            pre[3][cc] += xg[2 * H_ + k + cc];
            pre[4][cc] += xg[3 * H_ + k + cc];
        }
        #pragma unroll
        for (int cc = 0; cc < 2; cc++) {
            float fl = sigmoidf_(pre[0][cc]);
            float fr = sigmoidf_(pre[1][cc]);
            float ig = sigmoidf_(pre[2][cc]);
            float og = sigmoidf_(pre[3][cc]);
            float ug = tanhf(pre[4][cc]);
            float cl = cin[(2 * r) * H_ + k + cc];
            float cr = cin[(2 * r + 1) * H_ + k + cc];
            float cv = ig * ug + fl * cl + fr * cr;
            cout[r * H_ + k + cc] = cv;
            hout[r * H_ + k + cc] = og * tanhf(cv);
        }
    }
}

// ---------------- final: root_hidden + scores -----------------------------
// out layout: [0 .. B*3) scores, [B*3 .. B*3 + B*512) root_hidden
__global__ void final_kernel(const float* __restrict__ Ws,
                             const float* __restrict__ bs,
                             float* __restrict__ out, int buf) {
    __shared__ float red[512];
    int b = blockIdx.x;
    int t = threadIdx.x;                 // 512 threads
    const float* h = g_h[buf];
    float rh = h[(b * 2 + (t >> 8)) * H_ + (t & 255)];
    out[B_ * 3 + b * 512 + t] = rh;
    #pragma unroll
    for (int s = 0; s < 3; s++) {
        red[t] = rh * Ws[t * 3 + s];
        __syncthreads();
        for (int st = 256; st > 0; st >>= 1) {
            if (t < st) red[t] += red[t + st];
            __syncthreads();
        }
        if (t == 0) out[b * 3 + s] = red[0] + bs[s];
        __syncthreads();
    }
}

// ---------------- launcher ------------------------------------------------
extern "C" void kernel_launch(void* const* d_in, const int* in_sizes, int n_in,
                              void* d_out, int out_size) {
    const int*   ids = (const int*)d_in[0];
    const float* emb = (const float*)d_in[1];
    const float* W   = (const float*)d_in[2];
    const float* bW  = (const float*)d_in[3];
    const float* U   = (const float*)d_in[4];
    const float* Ws  = (const float*)d_in[5];
    const float* bs  = (const float*)d_in[6];
    float* out = (float*)d_out;

    xg_kernel<<<V_, 256>>>(emb, W, bW);
    ucat_kernel<<<(512 * 1280 + 255) / 256, 256>>>(U);
    leaf_kernel<<<(B_ * 1024 * H_) / 256, 256>>>(ids);

    int cur = 0;
    for (int lev = 9; lev >= 1; lev--) {
        int n = 1 << lev;
        int M = B_ * n;
        dim3 grid(M / BM_, H_ / TK_);
        inner_kernel<<<grid, 256>>>(ids, n - 2, lev, cur, 1 - cur);
        cur = 1 - cur;
    }
    final_kernel<<<B_, 512>>>(Ws, bs, out, cur);
}